// round 1
// baseline (speedup 1.0000x reference)
#include <cuda_runtime.h>
#include <cuda_bf16.h>
#include <math.h>

// ---------------------------------------------------------------------------
// Net_23553600651528: conv1+relu -> conv2+relu+maxpool -> fc1+relu ->
// [fc2+sigmoid -> 10-qubit statevector sim -> <Y_k> -> log_softmax] fused.
// B = 2048 fixed.
// ---------------------------------------------------------------------------

#define BATCH 2048

// scratch buffers (allocation-free rule: __device__ globals)
__device__ float g_h1[BATCH * 32 * 26 * 26];   // conv1 output
__device__ float g_pool[BATCH * 9216];          // conv2+pool output (flattened NCHW)
__device__ float g_fc1[BATCH * 128];            // fc1 output

// ---------------------------------------------------------------------------
// conv1: in [B,1,28,28] -> out [B,32,26,26], relu
// one block per batch element, 256 threads
// ---------------------------------------------------------------------------
__global__ void conv1_kernel(const float* __restrict__ x,
                             const float* __restrict__ w,
                             const float* __restrict__ bias)
{
    __shared__ float sx[784];
    __shared__ float sw[288];
    __shared__ float sb[32];
    const int b = blockIdx.x;
    const int tid = threadIdx.x;

    for (int i = tid; i < 784; i += 256) sx[i] = x[b * 784 + i];
    for (int i = tid; i < 288; i += 256) sw[i] = w[i];
    if (tid < 32) sb[tid] = bias[tid];
    __syncthreads();

    float* outb = g_h1 + (size_t)b * 32 * 676;
    for (int p = tid; p < 676; p += 256) {
        const int oy = p / 26, ox = p % 26;
        float in[9];
#pragma unroll
        for (int kh = 0; kh < 3; kh++)
#pragma unroll
            for (int kw = 0; kw < 3; kw++)
                in[kh * 3 + kw] = sx[(oy + kh) * 28 + ox + kw];
#pragma unroll 4
        for (int oc = 0; oc < 32; oc++) {
            float a = sb[oc];
#pragma unroll
            for (int j = 0; j < 9; j++) a += sw[oc * 9 + j] * in[j];
            outb[oc * 676 + p] = fmaxf(a, 0.0f);
        }
    }
}

// ---------------------------------------------------------------------------
// conv2 + relu + 2x2 maxpool fused:
// in [B,32,26,26] -> conv [B,64,24,24] -> pooled [B,64,12,12]
// grid (B, 8): 8 output channels per block; 144 threads = one 2x2 quad each
// ---------------------------------------------------------------------------
__global__ void conv2_kernel(const float* __restrict__ w2,
                             const float* __restrict__ b2)
{
    __shared__ float sIn[16 * 676];   // 16 input channels chunk
    __shared__ float sW[8 * 144];     // 8 oc x 16 ic x 9

    const int b = blockIdx.x;
    const int ocg = blockIdx.y;       // 0..7 (8 oc each)
    const int tid = threadIdx.x;      // 0..143
    const int qy = tid / 12, qx = tid % 12;

    float acc[8][4];
#pragma unroll
    for (int oc = 0; oc < 8; oc++) {
        const float bv = b2[ocg * 8 + oc];
        acc[oc][0] = bv; acc[oc][1] = bv; acc[oc][2] = bv; acc[oc][3] = bv;
    }

    for (int c2 = 0; c2 < 2; c2++) {
        const int ic0 = c2 * 16;
        // channels contiguous -> one linear 10816-float block
        const float* src = g_h1 + ((size_t)b * 32 + ic0) * 676;
        for (int i = tid; i < 10816; i += 144) sIn[i] = src[i];
        for (int i = tid; i < 1152; i += 144) {
            const int oc = i / 144, r = i % 144;
            sW[i] = w2[(ocg * 8 + oc) * 288 + ic0 * 9 + r];
        }
        __syncthreads();

        for (int ic = 0; ic < 16; ic++) {
            const float* inc = sIn + ic * 676;
#pragma unroll
            for (int kh = 0; kh < 3; kh++) {
                const float* row0 = inc + (2 * qy + kh) * 26 + 2 * qx;
#pragma unroll
                for (int kw = 0; kw < 3; kw++) {
                    const float i00 = row0[kw];
                    const float i01 = row0[kw + 1];
                    const float i10 = row0[26 + kw];
                    const float i11 = row0[27 + kw];
                    const int wb = ic * 9 + kh * 3 + kw;
#pragma unroll
                    for (int oc = 0; oc < 8; oc++) {
                        const float wv = sW[oc * 144 + wb];
                        acc[oc][0] += wv * i00;
                        acc[oc][1] += wv * i01;
                        acc[oc][2] += wv * i10;
                        acc[oc][3] += wv * i11;
                    }
                }
            }
        }
        __syncthreads();
    }

#pragma unroll
    for (int oc = 0; oc < 8; oc++) {
        float m = fmaxf(fmaxf(acc[oc][0], acc[oc][1]), fmaxf(acc[oc][2], acc[oc][3]));
        m = fmaxf(m, 0.0f);
        g_pool[(size_t)b * 9216 + (ocg * 8 + oc) * 144 + qy * 12 + qx] = m;
    }
}

// ---------------------------------------------------------------------------
// fc1: [2048,9216] x [128,9216]^T -> [2048,128], +bias, relu
// block = 16 rows x 128 cols, 128 threads (4x4 outputs each), KC=32
// ---------------------------------------------------------------------------
__global__ void fc1_kernel(const float* __restrict__ W,
                           const float* __restrict__ bias)
{
    __shared__ float sA[32 * 16];
    __shared__ float sB[32 * 132];

    const int tid = threadIdx.x;
    const int m0 = blockIdx.x * 16;
    const int g = tid >> 5, lane = tid & 31;
    const int r0 = g * 4, c0 = lane * 4;

    float acc[4][4];
#pragma unroll
    for (int i = 0; i < 4; i++)
#pragma unroll
        for (int j = 0; j < 4; j++) acc[i][j] = 0.0f;

    const float* Ab = g_pool + (size_t)m0 * 9216;

    for (int k0 = 0; k0 < 9216; k0 += 32) {
        { // A tile: 16x32, transposed into sA[kc][m]
            const int m = tid >> 3;
            const int kc = (tid & 7) * 4;
            const float4 v = *(const float4*)(Ab + (size_t)m * 9216 + k0 + kc);
            sA[(kc + 0) * 16 + m] = v.x;
            sA[(kc + 1) * 16 + m] = v.y;
            sA[(kc + 2) * 16 + m] = v.z;
            sA[(kc + 3) * 16 + m] = v.w;
        }
#pragma unroll
        for (int j = 0; j < 8; j++) { // B tile: 128x32 transposed into sB[kc][n]
            const int idx = tid + j * 128;
            const int n = idx >> 3;
            const int kc = (idx & 7) * 4;
            const float4 v = *(const float4*)(W + (size_t)n * 9216 + k0 + kc);
            sB[(kc + 0) * 132 + n] = v.x;
            sB[(kc + 1) * 132 + n] = v.y;
            sB[(kc + 2) * 132 + n] = v.z;
            sB[(kc + 3) * 132 + n] = v.w;
        }
        __syncthreads();

#pragma unroll
        for (int kk = 0; kk < 32; kk++) {
            const float4 a4 = *(const float4*)(sA + kk * 16 + r0);
            const float4 b4 = *(const float4*)(sB + kk * 132 + c0);
            acc[0][0] += a4.x * b4.x; acc[0][1] += a4.x * b4.y;
            acc[0][2] += a4.x * b4.z; acc[0][3] += a4.x * b4.w;
            acc[1][0] += a4.y * b4.x; acc[1][1] += a4.y * b4.y;
            acc[1][2] += a4.y * b4.z; acc[1][3] += a4.y * b4.w;
            acc[2][0] += a4.z * b4.x; acc[2][1] += a4.z * b4.y;
            acc[2][2] += a4.z * b4.z; acc[2][3] += a4.z * b4.w;
            acc[3][0] += a4.w * b4.x; acc[3][1] += a4.w * b4.y;
            acc[3][2] += a4.w * b4.z; acc[3][3] += a4.w * b4.w;
        }
        __syncthreads();
    }

#pragma unroll
    for (int i = 0; i < 4; i++)
#pragma unroll
        for (int j = 0; j < 4; j++) {
            const int col = c0 + j;
            const float v = acc[i][j] + bias[col];
            g_fc1[(size_t)(m0 + r0 + i) * 128 + col] = fmaxf(v, 0.0f);
        }
}

// ---------------------------------------------------------------------------
// quantum kernel: fc2 + sigmoid*2pi, product-state init, entangling gates,
// <Y_k>, log_softmax. One block (256 threads) per batch element.
// wire w <-> bit (9-w): w0=512, w1=256, w2=128, w3=64, w4=32, w5=16,
//                       w6=8, w7=4, w8=2, w9=1
// ---------------------------------------------------------------------------
__device__ __forceinline__ float2 cmul(float2 a, float2 b) {
    return make_float2(a.x * b.x - a.y * b.y, a.x * b.y + a.y * b.x);
}
__device__ __forceinline__ float2 cadd(float2 a, float2 b) {
    return make_float2(a.x + b.x, a.y + b.y);
}

__global__ void qsim_kernel(const float* __restrict__ fc2w,
                            const float* __restrict__ fc2b,
                            const float* __restrict__ theta0,
                            const float* __restrict__ theta_rz,
                            const float* __restrict__ theta_ps,
                            const float* __restrict__ rot_p,
                            float* __restrict__ out)
{
    __shared__ float sh[128];
    __shared__ float sang[10];
    __shared__ float2 svec[10][2];
    __shared__ float2 psi[1024];
    __shared__ float sred[8];

    const int b = blockIdx.x;
    const int tid = threadIdx.x;
    const int wid = tid >> 5, lane = tid & 31;

    if (tid < 128) sh[tid] = g_fc1[(size_t)b * 128 + tid];
    __syncthreads();

    // fc2 + sigmoid*2pi and per-wire vectors (thread k handles wire k; the
    // merged RX angle for wire k only needs a[k], so no extra sync needed)
    if (tid < 10) {
        float z = fc2b[tid];
        const float* wr = fc2w + tid * 128;
        for (int k = 0; k < 128; k++) z += sh[k] * wr[k];
        const float a = 6.2831853071795864f / (1.0f + expf(-z));
        sang[tid] = a;

        // merged RX angle
        float alpha = theta0[tid] + a;
        if (tid == 1) alpha += a;                 // extra RX(a1) on wire 1
        if (tid == 5) alpha -= 0.78539816339745f; // RX(-pi/4) on wire 5
        const float c = cosf(0.5f * alpha);
        const float s = sinf(0.5f * alpha);
        float2 v0 = make_float2(c, 0.0f);
        float2 v1 = make_float2(0.0f, -s);

        if (tid == 2) { // RY(a2)
            const float cy = cosf(0.5f * a), sy = sinf(0.5f * a);
            v0 = make_float2(cy * c, sy * s);
            v1 = make_float2(sy * c, -cy * s);
        } else if (tid == 3) { // RZ(a3)
            const float2 e = make_float2(cosf(0.5f * a), -sinf(0.5f * a));
            v0 = cmul(v0, e);
            v1 = cmul(v1, make_float2(e.x, -e.y));
        } else if (tid == 4) { // S
            v1 = make_float2(s, 0.0f);
        } else if (tid == 5) { // T
            const float r = 0.70710678118654752f;
            v1 = make_float2(s * r, -s * r);
        } else if (tid == 6) { // RZ(theta_rz)
            const float t = theta_rz[0];
            const float2 e = make_float2(cosf(0.5f * t), -sinf(0.5f * t));
            v0 = cmul(v0, e);
            v1 = cmul(v1, make_float2(e.x, -e.y));
        } else if (tid == 7) { // SX
            const float h0 = 0.5f * (c - s), h1 = 0.5f * (c + s);
            v0 = make_float2(h0, h0);
            v1 = make_float2(h1, -h1);
        }
        svec[tid][0] = v0;
        svec[tid][1] = v1;
    }
    __syncthreads();

    // product-state init + composed diagonal CZ*CNOT*CY(0,5) = -i on bit512
    for (int i = tid; i < 1024; i += 256) {
        float2 p = svec[0][(i >> 9) & 1];
#pragma unroll
        for (int k = 1; k < 10; k++)
            p = cmul(p, svec[k][(i >> (9 - k)) & 1]);
        if (i & 512) p = make_float2(p.y, -p.x); // * (-i)
        psi[i] = p;
    }
    __syncthreads();

    // CY(3,8): control bit 64, target bit 2
    for (int p = tid; p < 512; p += 256) {
        const int i0 = ((p & ~1) << 1) | (p & 1);
        if (i0 & 64) {
            const int i1 = i0 | 2;
            const float2 t0 = psi[i0], t1 = psi[i1];
            psi[i0] = make_float2(t1.y, -t1.x);   // -i * t1
            psi[i1] = make_float2(-t0.y, t0.x);   //  i * t0
        }
    }
    __syncthreads();

    // SWAP(2,3): bits 128 & 64
    for (int i = tid; i < 1024; i += 256) {
        if ((i & 192) == 128) {
            const int j = i ^ 192;
            const float2 t = psi[i]; psi[i] = psi[j]; psi[j] = t;
        }
    }
    __syncthreads();

    // CSWAP(4;5,6): control 32, swap bits 16 & 8
    for (int i = tid; i < 1024; i += 256) {
        if ((i & 32) && ((i & 24) == 16)) {
            const int j = i ^ 24;
            const float2 t = psi[i]; psi[i] = psi[j]; psi[j] = t;
        }
    }
    __syncthreads();

    // TOFF(8,5;0): controls bits 2 & 16, target bit 512
    for (int p = tid; p < 512; p += 256) {
        if ((p & 18) == 18) {
            const int j = p | 512;
            const float2 t = psi[p]; psi[p] = psi[j]; psi[j] = t;
        }
    }
    __syncthreads();

    // diagonal phases: Phase(theta_ps) on wire8 (bit2), Phase(a7) on wire7 (bit4)
    {
        const float tps = theta_ps[0];
        const float a7 = sang[7];
        const float2 e8 = make_float2(cosf(tps), sinf(tps));
        const float2 e7 = make_float2(cosf(a7), sinf(a7));
        for (int i = tid; i < 1024; i += 256) {
            float2 v = psi[i];
            if (i & 2) v = cmul(v, e8);
            if (i & 4) v = cmul(v, e7);
            psi[i] = v;
        }
    }
    __syncthreads();

    // Rot(rot_p) on wire4 (bit 32)
    {
        const float phi = rot_p[0], th = rot_p[1], om = rot_p[2];
        const float c = cosf(0.5f * th), s = sinf(0.5f * th);
        const float hs = 0.5f * (phi + om), hd = 0.5f * (phi - om);
        const float2 m00 = make_float2(c * cosf(hs), -c * sinf(hs));
        const float2 m01 = make_float2(-s * cosf(hd), -s * sinf(hd));
        const float2 m10 = make_float2(s * cosf(hd), -s * sinf(hd));
        const float2 m11 = make_float2(c * cosf(hs), c * sinf(hs));
        for (int p = tid; p < 512; p += 256) {
            const int lo = p & 31;
            const int i0 = ((p - lo) << 1) | lo;
            const int i1 = i0 | 32;
            const float2 t0 = psi[i0], t1 = psi[i1];
            psi[i0] = cadd(cmul(m00, t0), cmul(m01, t1));
            psi[i1] = cadd(cmul(m10, t0), cmul(m11, t1));
        }
    }
    __syncthreads();

    // Rot(a6, a7, a8) on wire5 (bit 16)
    {
        const float phi = sang[6], th = sang[7], om = sang[8];
        const float c = cosf(0.5f * th), s = sinf(0.5f * th);
        const float hs = 0.5f * (phi + om), hd = 0.5f * (phi - om);
        const float2 m00 = make_float2(c * cosf(hs), -c * sinf(hs));
        const float2 m01 = make_float2(-s * cosf(hd), -s * sinf(hd));
        const float2 m10 = make_float2(s * cosf(hd), -s * sinf(hd));
        const float2 m11 = make_float2(c * cosf(hs), c * sinf(hs));
        for (int p = tid; p < 512; p += 256) {
            const int lo = p & 15;
            const int i0 = ((p - lo) << 1) | lo;
            const int i1 = i0 | 16;
            const float2 t0 = psi[i0], t1 = psi[i1];
            psi[i0] = cadd(cmul(m00, t0), cmul(m01, t1));
            psi[i1] = cadd(cmul(m10, t0), cmul(m11, t1));
        }
    }
    __syncthreads();

    // expectations <Y_k> = 2 * sum_pairs Im(conj(psi0)*psi1); deterministic reduce
    float ev[10];
#pragma unroll
    for (int k = 0; k < 10; k++) {
        const int bsh = 9 - k;
        const int mlo = (1 << bsh) - 1;
        float part = 0.0f;
        for (int p = tid; p < 512; p += 256) {
            const int i0 = ((p >> bsh) << (bsh + 1)) | (p & mlo);
            const int i1 = i0 | (1 << bsh);
            const float2 a0 = psi[i0], a1 = psi[i1];
            part += a0.x * a1.y - a0.y * a1.x;
        }
#pragma unroll
        for (int off = 16; off > 0; off >>= 1)
            part += __shfl_down_sync(0xffffffffu, part, off);
        if (lane == 0) sred[wid] = part;
        __syncthreads();
        if (tid == 0) {
            float s = 0.0f;
            for (int w = 0; w < 8; w++) s += sred[w];
            ev[k] = 2.0f * s;
        }
        __syncthreads();
    }

    if (tid == 0) {
        float m = ev[0];
#pragma unroll
        for (int k = 1; k < 10; k++) m = fmaxf(m, ev[k]);
        float ssum = 0.0f;
#pragma unroll
        for (int k = 0; k < 10; k++) ssum += expf(ev[k] - m);
        const float l = logf(ssum);
#pragma unroll
        for (int k = 0; k < 10; k++)
            out[(size_t)b * 10 + k] = ev[k] - m - l;
    }
}

// ---------------------------------------------------------------------------
// launch
// ---------------------------------------------------------------------------
extern "C" void kernel_launch(void* const* d_in, const int* in_sizes, int n_in,
                              void* d_out, int out_size)
{
    const float* x       = (const float*)d_in[0];
    const float* conv1_w = (const float*)d_in[1];
    const float* conv1_b = (const float*)d_in[2];
    const float* conv2_w = (const float*)d_in[3];
    const float* conv2_b = (const float*)d_in[4];
    const float* fc1_w   = (const float*)d_in[5];
    const float* fc1_b   = (const float*)d_in[6];
    const float* fc2_w   = (const float*)d_in[7];
    const float* fc2_b   = (const float*)d_in[8];
    const float* theta0  = (const float*)d_in[9];
    const float* theta_rz = (const float*)d_in[10];
    const float* theta_ps = (const float*)d_in[11];
    const float* rot_p   = (const float*)d_in[12];
    float* out = (float*)d_out;

    conv1_kernel<<<BATCH, 256>>>(x, conv1_w, conv1_b);
    conv2_kernel<<<dim3(BATCH, 8), 144>>>(conv2_w, conv2_b);
    fc1_kernel<<<BATCH / 16, 128>>>(fc1_w, fc1_b);
    qsim_kernel<<<BATCH, 256>>>(fc2_w, fc2_b, theta0, theta_rz, theta_ps, rot_p, out);
}

// round 2
// speedup vs baseline: 3.0290x; 3.0290x over previous
#include <cuda_runtime.h>
#include <cuda_bf16.h>
#include <math.h>
#include <stdint.h>

// ---------------------------------------------------------------------------
// Net_23553600651528: conv1+relu -> conv2(tf32 tensor-core)+relu+maxpool ->
// fc1(K-split) -> [fc2+sigmoid -> 10-qubit statevector -> <Y> -> log_softmax]
// B = 2048 fixed.
// ---------------------------------------------------------------------------

#define BATCH 2048

// scratch (__device__ globals; allocation-free rule)
__device__ float g_h1[BATCH * 32 * 26 * 26];     // conv1 output [b][ic][26][26]
__device__ float g_pool[BATCH * 9216];           // pooled conv2, [b][quad(144)][oc(64)]
__device__ float g_fc1[BATCH * 128];             // fc1 output
__device__ float g_part[8 * BATCH * 128];        // fc1 K-split partials
__device__ uint4 g_wfrag[36 * 4 * 32];           // conv2 weights in B-fragment layout (tf32)
__device__ float g_fc1wp[128 * 9216];            // fc1 weights, K permuted to [quad][oc]

__device__ __forceinline__ uint32_t f2tf(float x) {
    uint32_t r;
    asm("cvt.rna.tf32.f32 %0, %1;" : "=r"(r) : "f"(x));
    return r;
}

__device__ __forceinline__ void mma_tf32(float& c0, float& c1, float& c2, float& c3,
                                         uint32_t a0, uint32_t a1, uint32_t a2, uint32_t a3,
                                         uint32_t b0, uint32_t b1) {
    asm volatile("mma.sync.aligned.m16n8k8.row.col.f32.tf32.tf32.f32 "
                 "{%0,%1,%2,%3}, {%4,%5,%6,%7}, {%8,%9}, {%0,%1,%2,%3};"
                 : "+f"(c0), "+f"(c1), "+f"(c2), "+f"(c3)
                 : "r"(a0), "r"(a1), "r"(a2), "r"(a3), "r"(b0), "r"(b1));
}

// ---------------------------------------------------------------------------
// prep: conv2 weights -> tf32 B-fragment layout
// K ordering: k = r*32 + ic, r = kh*3+kw.  kstep s covers k = s*8 .. s*8+7.
// fragment n covers oc = n*8 .. n*8+7.  lane: b0 = W[k=s*8+lane%4][oc=n*8+lane/4],
// b1 = W[k=s*8+4+lane%4][same oc].  Packed pairs: uint4 = (b0_n,b1_n,b0_{n+1},b1_{n+1}).
// ---------------------------------------------------------------------------
__global__ void prep_wfrag_kernel(const float* __restrict__ w2)
{
    const int s = blockIdx.x;          // 0..35
    const int tid = threadIdx.x;       // 0..127
    const int p = tid >> 5;            // frag pair 0..3
    const int lane = tid & 31;
    const int ka = s * 8 + (lane & 3);
    const int kb = ka + 4;
    const int oc0 = (2 * p) * 8 + (lane >> 2);
    const int oc1 = oc0 + 8;
    const int ra = ka >> 5, ica = ka & 31;
    const int rb = kb >> 5, icb = kb & 31;
    uint4 v;
    v.x = f2tf(w2[oc0 * 288 + ica * 9 + ra]);
    v.y = f2tf(w2[oc0 * 288 + icb * 9 + rb]);
    v.z = f2tf(w2[oc1 * 288 + ica * 9 + ra]);
    v.w = f2tf(w2[oc1 * 288 + icb * 9 + rb]);
    g_wfrag[(s * 4 + p) * 32 + lane] = v;
}

// ---------------------------------------------------------------------------
// prep: fc1 weights permuted to k' = quad*64 + oc
// ---------------------------------------------------------------------------
__global__ void prep_fc1w_kernel(const float* __restrict__ fc1_w)
{
    const int i = blockIdx.x * 256 + threadIdx.x;   // 0 .. 128*9216-1
    const int n = i / 9216;
    const int kp = i - n * 9216;
    const int quad = kp >> 6;
    const int oc = kp & 63;
    g_fc1wp[i] = fc1_w[n * 9216 + oc * 144 + quad];
}

// ---------------------------------------------------------------------------
// conv1: [B,1,28,28] -> [B,32,26,26], relu. one block per batch, 256 threads.
// ---------------------------------------------------------------------------
__global__ void conv1_kernel(const float* __restrict__ x,
                             const float* __restrict__ w,
                             const float* __restrict__ bias)
{
    __shared__ float sx[784];
    __shared__ float sw[288];
    __shared__ float sb[32];
    const int b = blockIdx.x;
    const int tid = threadIdx.x;

    for (int i = tid; i < 784; i += 256) sx[i] = x[b * 784 + i];
    for (int i = tid; i < 288; i += 256) sw[i] = w[i];
    if (tid < 32) sb[tid] = bias[tid];
    __syncthreads();

    float* outb = g_h1 + (size_t)b * 32 * 676;
    for (int p = tid; p < 676; p += 256) {
        const int oy = p / 26, ox = p % 26;
        float in[9];
#pragma unroll
        for (int kh = 0; kh < 3; kh++)
#pragma unroll
            for (int kw = 0; kw < 3; kw++)
                in[kh * 3 + kw] = sx[(oy + kh) * 28 + ox + kw];
#pragma unroll 4
        for (int oc = 0; oc < 32; oc++) {
            float a = sb[oc];
#pragma unroll
            for (int j = 0; j < 9; j++) a += sw[oc * 9 + j] * in[j];
            outb[oc * 676 + p] = fmaxf(a, 0.0f);
        }
    }
}

// ---------------------------------------------------------------------------
// conv2 tensor-core: per batch GEMM C[576,64] = im2col[576,288] x W^T, tf32.
// M ordering: pos = quad*4 + e, quad = qy*12+qx (pool quad), e = 2x2 element.
// relu+bias+2x2 maxpool fused via shfl_xor; output [b][quad][oc] to g_pool.
// 8 warps, warp w owns M rows 16w..16w+15 of each 128-row tile; 5 tiles
// (last tile: warps 0-3 only).  Dynamic smem: whole conv1 act (21632 f).
// ---------------------------------------------------------------------------
__global__ void __launch_bounds__(256) conv2_kernel(const float* __restrict__ b2)
{
    extern __shared__ float smem[];
    float* sIn = smem;            // 32*676 = 21632 floats
    float* sBias = smem + 21632;  // 64 floats

    const int b = blockIdx.x;
    const int tid = threadIdx.x;
    const int w = tid >> 5;
    const int lane = tid & 31;

    // stage conv1 output for this batch (coalesced float4)
    {
        const float4* src = (const float4*)(g_h1 + (size_t)b * 21632);
        float4* dst = (float4*)sIn;
        for (int i = tid; i < 5408; i += 256) dst[i] = src[i];
        if (tid < 64) sBias[tid] = b2[tid];
    }
    __syncthreads();

    const int cA = lane & 3;              // A col within half (ic low bits)
    const int rl0 = lane >> 2;            // A row 0 (of 16)
    float* outB = g_pool + (size_t)b * 9216;

    for (int t = 0; t < 5; t++) {
        if (t == 4 && w >= 4) break;      // 576 = 4*128 + 64 rows
        // per-thread spatial offsets for its two A rows
        int off0, off1;
        {
            const int qb = t * 32 + w * 4;
            int rl = rl0;
            int quad = qb + (rl >> 2), e = rl & 3;
            int qy = quad / 12, qx = quad - qy * 12;
            off0 = (2 * qy + (e >> 1)) * 26 + 2 * qx + (e & 1);
            rl = rl0 + 8;
            quad = qb + (rl >> 2); e = rl & 3;
            qy = quad / 12; qx = quad - qy * 12;
            off1 = (2 * qy + (e >> 1)) * 26 + 2 * qx + (e & 1);
        }

        float c[8][4];
#pragma unroll
        for (int n = 0; n < 8; n++) {
            c[n][0] = 0.f; c[n][1] = 0.f; c[n][2] = 0.f; c[n][3] = 0.f;
        }

        for (int ch = 0; ch < 9; ch++) {          // (kh,kw)
            const int khw = (ch / 3) * 26 + (ch % 3);
            const int base0 = cA * 676 + off0 + khw;
            const int base1 = cA * 676 + off1 + khw;
#pragma unroll
            for (int sub = 0; sub < 4; sub++) {   // ic groups of 8
                const int icoff = sub * 8 * 676;
                const uint32_t a0 = f2tf(sIn[base0 + icoff]);
                const uint32_t a1 = f2tf(sIn[base1 + icoff]);
                const uint32_t a2 = f2tf(sIn[base0 + icoff + 2704]);
                const uint32_t a3 = f2tf(sIn[base1 + icoff + 2704]);
                const int s = ch * 4 + sub;
                const uint4* wf = g_wfrag + s * 128;
#pragma unroll
                for (int p = 0; p < 4; p++) {
                    const uint4 bq = wf[p * 32 + lane];
                    mma_tf32(c[2 * p][0], c[2 * p][1], c[2 * p][2], c[2 * p][3],
                             a0, a1, a2, a3, bq.x, bq.y);
                    mma_tf32(c[2 * p + 1][0], c[2 * p + 1][1], c[2 * p + 1][2], c[2 * p + 1][3],
                             a0, a1, a2, a3, bq.z, bq.w);
                }
            }
        }

        // epilogue: 2x2 maxpool across the 4 rows of each quad via shfl_xor,
        // then bias + relu, store [quad][oc] (float2, coalesced 32B groups)
        const int h = lane >> 4;          // row-group within c01/c23
        const int r = lane & 3;           // col pair
        const bool writer = ((lane & 12) == 0);
        const int qb = t * 32 + w * 4;
#pragma unroll
        for (int n = 0; n < 8; n++) {
            float v0 = c[n][0], v1 = c[n][1], v2 = c[n][2], v3 = c[n][3];
#pragma unroll
            for (int d = 4; d <= 8; d <<= 1) {
                v0 = fmaxf(v0, __shfl_xor_sync(0xffffffffu, v0, d));
                v1 = fmaxf(v1, __shfl_xor_sync(0xffffffffu, v1, d));
                v2 = fmaxf(v2, __shfl_xor_sync(0xffffffffu, v2, d));
                v3 = fmaxf(v3, __shfl_xor_sync(0xffffffffu, v3, d));
            }
            if (writer) {
                const int oc = n * 8 + 2 * r;
                const float ba = sBias[oc], bb = sBias[oc + 1];
                float2 o01 = make_float2(fmaxf(v0 + ba, 0.f), fmaxf(v1 + bb, 0.f));
                float2 o23 = make_float2(fmaxf(v2 + ba, 0.f), fmaxf(v3 + bb, 0.f));
                *(float2*)(outB + (qb + h) * 64 + oc) = o01;
                *(float2*)(outB + (qb + 2 + h) * 64 + oc) = o23;
            }
        }
    }
}

// ---------------------------------------------------------------------------
// fc1 with K-split: partials[ks][2048][128], ks = 0..7, K chunk 1152.
// block: 32 rows x 128 cols, 256 threads (each 4x4).
// ---------------------------------------------------------------------------
__global__ void fc1_part_kernel()
{
    __shared__ float sA[32 * 36];
    __shared__ float sB[32 * 132];

    const int tid = threadIdx.x;
    const int M0 = blockIdx.x * 32;
    const int ks = blockIdx.y;
    const int kbase = ks * 1152;
    const int r0 = (tid >> 5) * 4;
    const int c0 = (tid & 31) * 4;

    float acc[4][4];
#pragma unroll
    for (int i = 0; i < 4; i++)
#pragma unroll
        for (int j = 0; j < 4; j++) acc[i][j] = 0.0f;

    for (int k0 = kbase; k0 < kbase + 1152; k0 += 32) {
        { // A tile 32x32 -> transposed sA[k][m]
            const int m = tid >> 3;
            const int kc = (tid & 7) * 4;
            const float4 v = *(const float4*)(g_pool + (size_t)(M0 + m) * 9216 + k0 + kc);
            sA[(kc + 0) * 36 + m] = v.x;
            sA[(kc + 1) * 36 + m] = v.y;
            sA[(kc + 2) * 36 + m] = v.z;
            sA[(kc + 3) * 36 + m] = v.w;
        }
#pragma unroll
        for (int j = 0; j < 4; j++) { // B tile 128x32 -> sB[k][n]
            const int idx = tid + j * 256;
            const int n = idx >> 3;
            const int kc = (idx & 7) * 4;
            const float4 v = *(const float4*)(g_fc1wp + (size_t)n * 9216 + k0 + kc);
            sB[(kc + 0) * 132 + n] = v.x;
            sB[(kc + 1) * 132 + n] = v.y;
            sB[(kc + 2) * 132 + n] = v.z;
            sB[(kc + 3) * 132 + n] = v.w;
        }
        __syncthreads();

#pragma unroll
        for (int kk = 0; kk < 32; kk++) {
            const float4 a4 = *(const float4*)(sA + kk * 36 + r0);
            const float4 b4 = *(const float4*)(sB + kk * 132 + c0);
            acc[0][0] += a4.x * b4.x; acc[0][1] += a4.x * b4.y;
            acc[0][2] += a4.x * b4.z; acc[0][3] += a4.x * b4.w;
            acc[1][0] += a4.y * b4.x; acc[1][1] += a4.y * b4.y;
            acc[1][2] += a4.y * b4.z; acc[1][3] += a4.y * b4.w;
            acc[2][0] += a4.z * b4.x; acc[2][1] += a4.z * b4.y;
            acc[2][2] += a4.z * b4.z; acc[2][3] += a4.z * b4.w;
            acc[3][0] += a4.w * b4.x; acc[3][1] += a4.w * b4.y;
            acc[3][2] += a4.w * b4.z; acc[3][3] += a4.w * b4.w;
        }
        __syncthreads();
    }

    float* dst = g_part + (size_t)ks * BATCH * 128;
#pragma unroll
    for (int i = 0; i < 4; i++)
        *(float4*)(dst + (size_t)(M0 + r0 + i) * 128 + c0) =
            make_float4(acc[i][0], acc[i][1], acc[i][2], acc[i][3]);
}

__global__ void fc1_reduce_kernel(const float* __restrict__ bias)
{
    const int i = blockIdx.x * 256 + threadIdx.x;  // 0 .. 2048*128-1
    float s = 0.0f;
#pragma unroll
    for (int ks = 0; ks < 8; ks++) s += g_part[(size_t)ks * BATCH * 128 + i];
    s += bias[i & 127];
    g_fc1[i] = fmaxf(s, 0.0f);
}

// ---------------------------------------------------------------------------
// quantum kernel (unchanged from round 1); wire w <-> bit (9-w)
// ---------------------------------------------------------------------------
__device__ __forceinline__ float2 cmul(float2 a, float2 b) {
    return make_float2(a.x * b.x - a.y * b.y, a.x * b.y + a.y * b.x);
}
__device__ __forceinline__ float2 cadd(float2 a, float2 b) {
    return make_float2(a.x + b.x, a.y + b.y);
}

__global__ void qsim_kernel(const float* __restrict__ fc2w,
                            const float* __restrict__ fc2b,
                            const float* __restrict__ theta0,
                            const float* __restrict__ theta_rz,
                            const float* __restrict__ theta_ps,
                            const float* __restrict__ rot_p,
                            float* __restrict__ out)
{
    __shared__ float sh[128];
    __shared__ float sang[10];
    __shared__ float2 svec[10][2];
    __shared__ float2 psi[1024];
    __shared__ float sred[8];

    const int b = blockIdx.x;
    const int tid = threadIdx.x;
    const int wid = tid >> 5, lane = tid & 31;

    if (tid < 128) sh[tid] = g_fc1[(size_t)b * 128 + tid];
    __syncthreads();

    if (tid < 10) {
        float z = fc2b[tid];
        const float* wr = fc2w + tid * 128;
        for (int k = 0; k < 128; k++) z += sh[k] * wr[k];
        const float a = 6.2831853071795864f / (1.0f + expf(-z));
        sang[tid] = a;

        float alpha = theta0[tid] + a;
        if (tid == 1) alpha += a;
        if (tid == 5) alpha -= 0.78539816339745f;
        const float c = cosf(0.5f * alpha);
        const float s = sinf(0.5f * alpha);
        float2 v0 = make_float2(c, 0.0f);
        float2 v1 = make_float2(0.0f, -s);

        if (tid == 2) {
            const float cy = cosf(0.5f * a), sy = sinf(0.5f * a);
            v0 = make_float2(cy * c, sy * s);
            v1 = make_float2(sy * c, -cy * s);
        } else if (tid == 3) {
            const float2 e = make_float2(cosf(0.5f * a), -sinf(0.5f * a));
            v0 = cmul(v0, e);
            v1 = cmul(v1, make_float2(e.x, -e.y));
        } else if (tid == 4) {
            v1 = make_float2(s, 0.0f);
        } else if (tid == 5) {
            const float r = 0.70710678118654752f;
            v1 = make_float2(s * r, -s * r);
        } else if (tid == 6) {
            const float t = theta_rz[0];
            const float2 e = make_float2(cosf(0.5f * t), -sinf(0.5f * t));
            v0 = cmul(v0, e);
            v1 = cmul(v1, make_float2(e.x, -e.y));
        } else if (tid == 7) {
            const float h0 = 0.5f * (c - s), h1 = 0.5f * (c + s);
            v0 = make_float2(h0, h0);
            v1 = make_float2(h1, -h1);
        }
        svec[tid][0] = v0;
        svec[tid][1] = v1;
    }
    __syncthreads();

    for (int i = tid; i < 1024; i += 256) {
        float2 p = svec[0][(i >> 9) & 1];
#pragma unroll
        for (int k = 1; k < 10; k++)
            p = cmul(p, svec[k][(i >> (9 - k)) & 1]);
        if (i & 512) p = make_float2(p.y, -p.x);
        psi[i] = p;
    }
    __syncthreads();

    for (int p = tid; p < 512; p += 256) {
        const int i0 = ((p & ~1) << 1) | (p & 1);
        if (i0 & 64) {
            const int i1 = i0 | 2;
            const float2 t0 = psi[i0], t1 = psi[i1];
            psi[i0] = make_float2(t1.y, -t1.x);
            psi[i1] = make_float2(-t0.y, t0.x);
        }
    }
    __syncthreads();

    for (int i = tid; i < 1024; i += 256) {
        if ((i & 192) == 128) {
            const int j = i ^ 192;
            const float2 t = psi[i]; psi[i] = psi[j]; psi[j] = t;
        }
    }
    __syncthreads();

    for (int i = tid; i < 1024; i += 256) {
        if ((i & 32) && ((i & 24) == 16)) {
            const int j = i ^ 24;
            const float2 t = psi[i]; psi[i] = psi[j]; psi[j] = t;
        }
    }
    __syncthreads();

    for (int p = tid; p < 512; p += 256) {
        if ((p & 18) == 18) {
            const int j = p | 512;
            const float2 t = psi[p]; psi[p] = psi[j]; psi[j] = t;
        }
    }
    __syncthreads();

    {
        const float tps = theta_ps[0];
        const float a7 = sang[7];
        const float2 e8 = make_float2(cosf(tps), sinf(tps));
        const float2 e7 = make_float2(cosf(a7), sinf(a7));
        for (int i = tid; i < 1024; i += 256) {
            float2 v = psi[i];
            if (i & 2) v = cmul(v, e8);
            if (i & 4) v = cmul(v, e7);
            psi[i] = v;
        }
    }
    __syncthreads();

    {
        const float phi = rot_p[0], th = rot_p[1], om = rot_p[2];
        const float c = cosf(0.5f * th), s = sinf(0.5f * th);
        const float hs = 0.5f * (phi + om), hd = 0.5f * (phi - om);
        const float2 m00 = make_float2(c * cosf(hs), -c * sinf(hs));
        const float2 m01 = make_float2(-s * cosf(hd), -s * sinf(hd));
        const float2 m10 = make_float2(s * cosf(hd), -s * sinf(hd));
        const float2 m11 = make_float2(c * cosf(hs), c * sinf(hs));
        for (int p = tid; p < 512; p += 256) {
            const int lo = p & 31;
            const int i0 = ((p - lo) << 1) | lo;
            const int i1 = i0 | 32;
            const float2 t0 = psi[i0], t1 = psi[i1];
            psi[i0] = cadd(cmul(m00, t0), cmul(m01, t1));
            psi[i1] = cadd(cmul(m10, t0), cmul(m11, t1));
        }
    }
    __syncthreads();

    {
        const float phi = sang[6], th = sang[7], om = sang[8];
        const float c = cosf(0.5f * th), s = sinf(0.5f * th);
        const float hs = 0.5f * (phi + om), hd = 0.5f * (phi - om);
        const float2 m00 = make_float2(c * cosf(hs), -c * sinf(hs));
        const float2 m01 = make_float2(-s * cosf(hd), -s * sinf(hd));
        const float2 m10 = make_float2(s * cosf(hd), -s * sinf(hd));
        const float2 m11 = make_float2(c * cosf(hs), c * sinf(hs));
        for (int p = tid; p < 512; p += 256) {
            const int lo = p & 15;
            const int i0 = ((p - lo) << 1) | lo;
            const int i1 = i0 | 16;
            const float2 t0 = psi[i0], t1 = psi[i1];
            psi[i0] = cadd(cmul(m00, t0), cmul(m01, t1));
            psi[i1] = cadd(cmul(m10, t0), cmul(m11, t1));
        }
    }
    __syncthreads();

    float ev[10];
#pragma unroll
    for (int k = 0; k < 10; k++) {
        const int bsh = 9 - k;
        const int mlo = (1 << bsh) - 1;
        float part = 0.0f;
        for (int p = tid; p < 512; p += 256) {
            const int i0 = ((p >> bsh) << (bsh + 1)) | (p & mlo);
            const int i1 = i0 | (1 << bsh);
            const float2 a0 = psi[i0], a1 = psi[i1];
            part += a0.x * a1.y - a0.y * a1.x;
        }
#pragma unroll
        for (int off = 16; off > 0; off >>= 1)
            part += __shfl_down_sync(0xffffffffu, part, off);
        if (lane == 0) sred[wid] = part;
        __syncthreads();
        if (tid == 0) {
            float s = 0.0f;
            for (int w = 0; w < 8; w++) s += sred[w];
            ev[k] = 2.0f * s;
        }
        __syncthreads();
    }

    if (tid == 0) {
        float m = ev[0];
#pragma unroll
        for (int k = 1; k < 10; k++) m = fmaxf(m, ev[k]);
        float ssum = 0.0f;
#pragma unroll
        for (int k = 0; k < 10; k++) ssum += expf(ev[k] - m);
        const float l = logf(ssum);
#pragma unroll
        for (int k = 0; k < 10; k++)
            out[(size_t)b * 10 + k] = ev[k] - m - l;
    }
}

// ---------------------------------------------------------------------------
// launch
// ---------------------------------------------------------------------------
extern "C" void kernel_launch(void* const* d_in, const int* in_sizes, int n_in,
                              void* d_out, int out_size)
{
    const float* x        = (const float*)d_in[0];
    const float* conv1_w  = (const float*)d_in[1];
    const float* conv1_b  = (const float*)d_in[2];
    const float* conv2_w  = (const float*)d_in[3];
    const float* conv2_b  = (const float*)d_in[4];
    const float* fc1_w    = (const float*)d_in[5];
    const float* fc1_b    = (const float*)d_in[6];
    const float* fc2_w    = (const float*)d_in[7];
    const float* fc2_b    = (const float*)d_in[8];
    const float* theta0   = (const float*)d_in[9];
    const float* theta_rz = (const float*)d_in[10];
    const float* theta_ps = (const float*)d_in[11];
    const float* rot_p    = (const float*)d_in[12];
    float* out = (float*)d_out;

    const int conv2_smem = (21632 + 64) * sizeof(float);  // 86784 B
    cudaFuncSetAttribute(conv2_kernel, cudaFuncAttributeMaxDynamicSharedMemorySize,
                         conv2_smem);

    prep_wfrag_kernel<<<36, 128>>>(conv2_w);
    prep_fc1w_kernel<<<(128 * 9216) / 256, 256>>>(fc1_w);
    conv1_kernel<<<BATCH, 256>>>(x, conv1_w, conv1_b);
    conv2_kernel<<<BATCH, 256, conv2_smem>>>(conv2_b);
    fc1_part_kernel<<<dim3(BATCH / 32, 8), 256>>>();
    fc1_reduce_kernel<<<(BATCH * 128) / 256, 256>>>(fc1_b);
    qsim_kernel<<<BATCH, 256>>>(fc2_w, fc2_b, theta0, theta_rz, theta_ps, rot_p, out);
}

// round 4
// speedup vs baseline: 4.7412x; 1.5653x over previous
#include <cuda_runtime.h>
#include <cuda_bf16.h>
#include <math.h>
#include <stdint.h>

// ---------------------------------------------------------------------------
// Net_23553600651528: [conv1+relu fused into conv2 block] ->
// conv2(bf16 tensor-core)+relu+maxpool -> fc1(K-split) ->
// [fc2+sigmoid -> 10-qubit statevector -> <Y> -> log_softmax].  B = 2048.
// ---------------------------------------------------------------------------

#define BATCH 2048

// scratch (__device__ globals; allocation-free rule)
__device__ float g_pool[BATCH * 9216];           // pooled conv2, [b][quad(144)][oc(64)]
__device__ float g_fc1[BATCH * 128];             // fc1 output
__device__ float g_part[8 * BATCH * 128];        // fc1 K-split partials
__device__ uint4 g_wfragb[18 * 4 * 32];          // conv2 weights, bf16 B-fragment layout
__device__ float g_fc1wp[128 * 9216];            // fc1 weights, K permuted to [quad][oc]

__device__ __forceinline__ uint32_t packbf(float lo, float hi) {
    __nv_bfloat162 h2 = __floats2bfloat162_rn(lo, hi);   // .x=lo -> low 16 bits
    return *reinterpret_cast<uint32_t*>(&h2);
}

__device__ __forceinline__ void mma_bf16(float& c0, float& c1, float& c2, float& c3,
                                         uint32_t a0, uint32_t a1, uint32_t a2, uint32_t a3,
                                         uint32_t b0, uint32_t b1) {
    asm volatile("mma.sync.aligned.m16n8k16.row.col.f32.bf16.bf16.f32 "
                 "{%0,%1,%2,%3}, {%4,%5,%6,%7}, {%8,%9}, {%0,%1,%2,%3};"
                 : "+f"(c0), "+f"(c1), "+f"(c2), "+f"(c3)
                 : "r"(a0), "r"(a1), "r"(a2), "r"(a3), "r"(b0), "r"(b1));
}

// ---------------------------------------------------------------------------
// prep: conv2 weights -> bf16 B-fragment layout for m16n8k16.
// K ordering: k = r*32 + ic, r = kh*3+kw.  k-step s (0..17): r = s>>1,
// icb = (s&1)*16.  Fragment n covers oc = n*8..n*8+7; lane (g=lane>>2, c=lane&3):
//   b0 = {W[k=2c][n=g], W[k=2c+1][n=g]},  b1 = {W[k=2c+8], W[k=2c+9]}  (k rel. step)
// Packed pairs: uint4 = (b0_n, b1_n, b0_{n+1}, b1_{n+1}), frag pairs p=0..3.
// ---------------------------------------------------------------------------
__global__ void prep_wfrag_kernel(const float* __restrict__ w2)
{
    const int s = blockIdx.x;          // 0..17
    const int tid = threadIdx.x;       // 0..127
    const int p = tid >> 5;            // frag pair
    const int lane = tid & 31;
    const int g = lane >> 2, c = lane & 3;
    const int r = s >> 1;
    const int icb = (s & 1) * 16;
    const int oc_a = (2 * p) * 8 + g;
    const int oc_b = oc_a + 8;
    const int i00 = icb + 2 * c, i01 = i00 + 1;
    const int i10 = i00 + 8,     i11 = i10 + 1;
#define WV(ic, oc) w2[(oc) * 288 + (ic) * 9 + r]
    uint4 v;
    v.x = packbf(WV(i00, oc_a), WV(i01, oc_a));
    v.y = packbf(WV(i10, oc_a), WV(i11, oc_a));
    v.z = packbf(WV(i00, oc_b), WV(i01, oc_b));
    v.w = packbf(WV(i10, oc_b), WV(i11, oc_b));
#undef WV
    g_wfragb[(s * 4 + p) * 32 + lane] = v;
}

// ---------------------------------------------------------------------------
// prep: fc1 weights permuted to k' = quad*64 + oc
// ---------------------------------------------------------------------------
__global__ void prep_fc1w_kernel(const float* __restrict__ fc1_w)
{
    const int i = blockIdx.x * 256 + threadIdx.x;   // 0 .. 128*9216-1
    const int n = i / 9216;
    const int kp = i - n * 9216;
    const int quad = kp >> 6;
    const int oc = kp & 63;
    g_fc1wp[i] = fc1_w[n * 9216 + oc * 144 + quad];
}

// ---------------------------------------------------------------------------
// fused conv1+conv2: one block per batch element, 256 threads.
//   phase 1: stage x [28x28] + conv1 weights, compute conv1+relu -> smem bf16
//            position-major layout sIn[pos*34 + ic]  (pad 32->34, 17-word rows)
//   phase 2: per-batch GEMM C[576,64] = im2col[576, 288] x W^T via bf16 mma
//            m16n8k16, M ordered pool-quad-major; bias+relu+2x2 maxpool in
//            registers via shfl_xor; store [quad][oc] fp32 to g_pool.
// ---------------------------------------------------------------------------
__global__ void __launch_bounds__(256) conv12_kernel(const float* __restrict__ x,
                                                     const float* __restrict__ w1,
                                                     const float* __restrict__ b1,
                                                     const float* __restrict__ b2)
{
    extern __shared__ char smem[];
    __nv_bfloat16* sIn = (__nv_bfloat16*)smem;            // 676*34 bf16 = 45968 B
    float* sx  = (float*)(smem + 45968);                  // 784 f
    float* sw1 = (float*)(smem + 45968 + 3136);           // 288 f
    float* sb1 = (float*)(smem + 45968 + 3136 + 1152);    // 32 f
    float* sb2 = (float*)(smem + 45968 + 3136 + 1152 + 128); // 64 f

    const int b = blockIdx.x;
    const int tid = threadIdx.x;
    const int w = tid >> 5;
    const int lane = tid & 31;

    // ---- stage inputs ----
    for (int i = tid; i < 784; i += 256) sx[i] = x[b * 784 + i];
    for (int i = tid; i < 288; i += 256) sw1[i] = w1[i];
    if (tid < 32) sb1[tid] = b1[tid];
    for (int i = tid; i < 64; i += 256) sb2[i] = b2[i];
    __syncthreads();

    // ---- conv1 + relu -> sIn (bf16, position-major, stride 34) ----
    for (int p = tid; p < 676; p += 256) {
        const int oy = p / 26, ox = p % 26;
        float in[9];
#pragma unroll
        for (int kh = 0; kh < 3; kh++)
#pragma unroll
            for (int kw = 0; kw < 3; kw++)
                in[kh * 3 + kw] = sx[(oy + kh) * 28 + ox + kw];
        uint32_t* dst = (uint32_t*)(sIn + p * 34);
#pragma unroll 4
        for (int oc2 = 0; oc2 < 16; oc2++) {
            float va = sb1[2 * oc2], vb = sb1[2 * oc2 + 1];
            const float* wa = sw1 + (2 * oc2) * 9;
#pragma unroll
            for (int j = 0; j < 9; j++) { va += wa[j] * in[j]; vb += wa[9 + j] * in[j]; }
            dst[oc2] = packbf(fmaxf(va, 0.0f), fmaxf(vb, 0.0f));
        }
    }
    __syncthreads();

    // ---- conv2 GEMM ----
    const uint32_t* sIn32 = (const uint32_t*)sIn;   // 17 words per position
    const int c = lane & 3;
    const int rl0 = lane >> 2;
    float* outB = g_pool + (size_t)b * 9216;

    for (int t = 0; t < 5; t++) {
        if (t == 4 && w >= 4) break;      // 576 = 4*128 + 64 rows
        int off0, off1;
        {
            const int qb = t * 32 + w * 4;
            int rl = rl0;
            int quad = qb + (rl >> 2), e = rl & 3;
            int qy = quad / 12, qx = quad - qy * 12;
            off0 = (2 * qy + (e >> 1)) * 26 + 2 * qx + (e & 1);
            rl = rl0 + 8;
            quad = qb + (rl >> 2); e = rl & 3;
            qy = quad / 12; qx = quad - qy * 12;
            off1 = (2 * qy + (e >> 1)) * 26 + 2 * qx + (e & 1);
        }
        const int w0 = off0 * 17 + c;
        const int w1b = off1 * 17 + c;

        float acc[8][4];
#pragma unroll
        for (int n = 0; n < 8; n++) {
            acc[n][0] = 0.f; acc[n][1] = 0.f; acc[n][2] = 0.f; acc[n][3] = 0.f;
        }

#pragma unroll
        for (int r = 0; r < 9; r++) {
            const int khw17 = ((r / 3) * 26 + (r % 3)) * 17;
#pragma unroll
            for (int h = 0; h < 2; h++) {            // ic halves (icb = h*16)
                const int base = khw17 + h * 8;
                const uint32_t a0 = sIn32[w0 + base];
                const uint32_t a1 = sIn32[w1b + base];
                const uint32_t a2 = sIn32[w0 + base + 4];
                const uint32_t a3 = sIn32[w1b + base + 4];
                const uint4* wf = g_wfragb + ((r * 2 + h) * 4) * 32;
#pragma unroll
                for (int p4 = 0; p4 < 4; p4++) {
                    const uint4 bq = wf[p4 * 32 + lane];
                    mma_bf16(acc[2 * p4][0], acc[2 * p4][1], acc[2 * p4][2], acc[2 * p4][3],
                             a0, a1, a2, a3, bq.x, bq.y);
                    mma_bf16(acc[2 * p4 + 1][0], acc[2 * p4 + 1][1],
                             acc[2 * p4 + 1][2], acc[2 * p4 + 1][3],
                             a0, a1, a2, a3, bq.z, bq.w);
                }
            }
        }

        // epilogue: 2x2 maxpool across quad rows via shfl_xor, bias+relu, store
        const int h = lane >> 4;
        const int rr = lane & 3;
        const bool writer = ((lane & 12) == 0);
        const int qb = t * 32 + w * 4;
#pragma unroll
        for (int n = 0; n < 8; n++) {
            float v0 = acc[n][0], v1 = acc[n][1], v2 = acc[n][2], v3 = acc[n][3];
#pragma unroll
            for (int d = 4; d <= 8; d <<= 1) {
                v0 = fmaxf(v0, __shfl_xor_sync(0xffffffffu, v0, d));
                v1 = fmaxf(v1, __shfl_xor_sync(0xffffffffu, v1, d));
                v2 = fmaxf(v2, __shfl_xor_sync(0xffffffffu, v2, d));
                v3 = fmaxf(v3, __shfl_xor_sync(0xffffffffu, v3, d));
            }
            if (writer) {
                const int oc = n * 8 + 2 * rr;
                const float ba = sb2[oc], bb = sb2[oc + 1];
                float2 o01 = make_float2(fmaxf(v0 + ba, 0.f), fmaxf(v1 + bb, 0.f));
                float2 o23 = make_float2(fmaxf(v2 + ba, 0.f), fmaxf(v3 + bb, 0.f));
                *(float2*)(outB + (qb + h) * 64 + oc) = o01;
                *(float2*)(outB + (qb + 2 + h) * 64 + oc) = o23;
            }
        }
    }
}

// ---------------------------------------------------------------------------
// fc1 with K-split: partials[ks][2048][128], ks = 0..7, K chunk 1152.
// block: 32 rows x 128 cols, 256 threads (each 4x4).
// ---------------------------------------------------------------------------
__global__ void fc1_part_kernel()
{
    __shared__ float sA[32 * 36];
    __shared__ float sB[32 * 132];

    const int tid = threadIdx.x;
    const int M0 = blockIdx.x * 32;
    const int ks = blockIdx.y;
    const int kbase = ks * 1152;
    const int r0 = (tid >> 5) * 4;
    const int c0 = (tid & 31) * 4;

    float acc[4][4];
#pragma unroll
    for (int i = 0; i < 4; i++)
#pragma unroll
        for (int j = 0; j < 4; j++) acc[i][j] = 0.0f;

    for (int k0 = kbase; k0 < kbase + 1152; k0 += 32) {
        {
            const int m = tid >> 3;
            const int kc = (tid & 7) * 4;
            const float4 v = *(const float4*)(g_pool + (size_t)(M0 + m) * 9216 + k0 + kc);
            sA[(kc + 0) * 36 + m] = v.x;
            sA[(kc + 1) * 36 + m] = v.y;
            sA[(kc + 2) * 36 + m] = v.z;
            sA[(kc + 3) * 36 + m] = v.w;
        }
#pragma unroll
        for (int j = 0; j < 4; j++) {
            const int idx = tid + j * 256;
            const int n = idx >> 3;
            const int kc = (idx & 7) * 4;
            const float4 v = *(const float4*)(g_fc1wp + (size_t)n * 9216 + k0 + kc);
            sB[(kc + 0) * 132 + n] = v.x;
            sB[(kc + 1) * 132 + n] = v.y;
            sB[(kc + 2) * 132 + n] = v.z;
            sB[(kc + 3) * 132 + n] = v.w;
        }
        __syncthreads();

#pragma unroll
        for (int kk = 0; kk < 32; kk++) {
            const float4 a4 = *(const float4*)(sA + kk * 36 + r0);
            const float4 b4 = *(const float4*)(sB + kk * 132 + c0);
            acc[0][0] += a4.x * b4.x; acc[0][1] += a4.x * b4.y;
            acc[0][2] += a4.x * b4.z; acc[0][3] += a4.x * b4.w;
            acc[1][0] += a4.y * b4.x; acc[1][1] += a4.y * b4.y;
            acc[1][2] += a4.y * b4.z; acc[1][3] += a4.y * b4.w;
            acc[2][0] += a4.z * b4.x; acc[2][1] += a4.z * b4.y;
            acc[2][2] += a4.z * b4.z; acc[2][3] += a4.z * b4.w;
            acc[3][0] += a4.w * b4.x; acc[3][1] += a4.w * b4.y;
            acc[3][2] += a4.w * b4.z; acc[3][3] += a4.w * b4.w;
        }
        __syncthreads();
    }

    float* dst = g_part + (size_t)ks * BATCH * 128;
#pragma unroll
    for (int i = 0; i < 4; i++)
        *(float4*)(dst + (size_t)(M0 + r0 + i) * 128 + c0) =
            make_float4(acc[i][0], acc[i][1], acc[i][2], acc[i][3]);
}

__global__ void fc1_reduce_kernel(const float* __restrict__ bias)
{
    const int i = blockIdx.x * 256 + threadIdx.x;
    float s = 0.0f;
#pragma unroll
    for (int ks = 0; ks < 8; ks++) s += g_part[(size_t)ks * BATCH * 128 + i];
    s += bias[i & 127];
    g_fc1[i] = fmaxf(s, 0.0f);
}

// ---------------------------------------------------------------------------
// quantum kernel; wire w <-> bit (9-w)
// ---------------------------------------------------------------------------
__device__ __forceinline__ float2 cmul(float2 a, float2 b) {
    return make_float2(a.x * b.x - a.y * b.y, a.x * b.y + a.y * b.x);
}
__device__ __forceinline__ float2 cadd(float2 a, float2 b) {
    return make_float2(a.x + b.x, a.y + b.y);
}

__global__ void qsim_kernel(const float* __restrict__ fc2w,
                            const float* __restrict__ fc2b,
                            const float* __restrict__ theta0,
                            const float* __restrict__ theta_rz,
                            const float* __restrict__ theta_ps,
                            const float* __restrict__ rot_p,
                            float* __restrict__ out)
{
    __shared__ float sh[128];
    __shared__ float sang[10];
    __shared__ float2 svec[10][2];
    __shared__ float2 psi[1024];
    __shared__ float sred[8];

    const int b = blockIdx.x;
    const int tid = threadIdx.x;
    const int wid = tid >> 5, lane = tid & 31;

    if (tid < 128) sh[tid] = g_fc1[(size_t)b * 128 + tid];
    __syncthreads();

    if (tid < 10) {
        float z = fc2b[tid];
        const float* wr = fc2w + tid * 128;
        for (int k = 0; k < 128; k++) z += sh[k] * wr[k];
        const float a = 6.2831853071795864f / (1.0f + expf(-z));
        sang[tid] = a;

        float alpha = theta0[tid] + a;
        if (tid == 1) alpha += a;
        if (tid == 5) alpha -= 0.78539816339745f;
        const float c = cosf(0.5f * alpha);
        const float s = sinf(0.5f * alpha);
        float2 v0 = make_float2(c, 0.0f);
        float2 v1 = make_float2(0.0f, -s);

        if (tid == 2) {
            const float cy = cosf(0.5f * a), sy = sinf(0.5f * a);
            v0 = make_float2(cy * c, sy * s);
            v1 = make_float2(sy * c, -cy * s);
        } else if (tid == 3) {
            const float2 e = make_float2(cosf(0.5f * a), -sinf(0.5f * a));
            v0 = cmul(v0, e);
            v1 = cmul(v1, make_float2(e.x, -e.y));
        } else if (tid == 4) {
            v1 = make_float2(s, 0.0f);
        } else if (tid == 5) {
            const float r = 0.70710678118654752f;
            v1 = make_float2(s * r, -s * r);
        } else if (tid == 6) {
            const float t = theta_rz[0];
            const float2 e = make_float2(cosf(0.5f * t), -sinf(0.5f * t));
            v0 = cmul(v0, e);
            v1 = cmul(v1, make_float2(e.x, -e.y));
        } else if (tid == 7) {
            const float h0 = 0.5f * (c - s), h1 = 0.5f * (c + s);
            v0 = make_float2(h0, h0);
            v1 = make_float2(h1, -h1);
        }
        svec[tid][0] = v0;
        svec[tid][1] = v1;
    }
    __syncthreads();

    for (int i = tid; i < 1024; i += 256) {
        float2 p = svec[0][(i >> 9) & 1];
#pragma unroll
        for (int k = 1; k < 10; k++)
            p = cmul(p, svec[k][(i >> (9 - k)) & 1]);
        if (i & 512) p = make_float2(p.y, -p.x);
        psi[i] = p;
    }
    __syncthreads();

    for (int p = tid; p < 512; p += 256) {
        const int i0 = ((p & ~1) << 1) | (p & 1);
        if (i0 & 64) {
            const int i1 = i0 | 2;
            const float2 t0 = psi[i0], t1 = psi[i1];
            psi[i0] = make_float2(t1.y, -t1.x);
            psi[i1] = make_float2(-t0.y, t0.x);
        }
    }
    __syncthreads();

    for (int i = tid; i < 1024; i += 256) {
        if ((i & 192) == 128) {
            const int j = i ^ 192;
            const float2 t = psi[i]; psi[i] = psi[j]; psi[j] = t;
        }
    }
    __syncthreads();

    for (int i = tid; i < 1024; i += 256) {
        if ((i & 32) && ((i & 24) == 16)) {
            const int j = i ^ 24;
            const float2 t = psi[i]; psi[i] = psi[j]; psi[j] = t;
        }
    }
    __syncthreads();

    for (int p = tid; p < 512; p += 256) {
        if ((p & 18) == 18) {
            const int j = p | 512;
            const float2 t = psi[p]; psi[p] = psi[j]; psi[j] = t;
        }
    }
    __syncthreads();

    {
        const float tps = theta_ps[0];
        const float a7 = sang[7];
        const float2 e8 = make_float2(cosf(tps), sinf(tps));
        const float2 e7 = make_float2(cosf(a7), sinf(a7));
        for (int i = tid; i < 1024; i += 256) {
            float2 v = psi[i];
            if (i & 2) v = cmul(v, e8);
            if (i & 4) v = cmul(v, e7);
            psi[i] = v;
        }
    }
    __syncthreads();

    {
        const float phi = rot_p[0], th = rot_p[1], om = rot_p[2];
        const float c = cosf(0.5f * th), s = sinf(0.5f * th);
        const float hs = 0.5f * (phi + om), hd = 0.5f * (phi - om);
        const float2 m00 = make_float2(c * cosf(hs), -c * sinf(hs));
        const float2 m01 = make_float2(-s * cosf(hd), -s * sinf(hd));
        const float2 m10 = make_float2(s * cosf(hd), -s * sinf(hd));
        const float2 m11 = make_float2(c * cosf(hs), c * sinf(hs));
        for (int p = tid; p < 512; p += 256) {
            const int lo = p & 31;
            const int i0 = ((p - lo) << 1) | lo;
            const int i1 = i0 | 32;
            const float2 t0 = psi[i0], t1 = psi[i1];
            psi[i0] = cadd(cmul(m00, t0), cmul(m01, t1));
            psi[i1] = cadd(cmul(m10, t0), cmul(m11, t1));
        }
    }
    __syncthreads();

    {
        const float phi = sang[6], th = sang[7], om = sang[8];
        const float c = cosf(0.5f * th), s = sinf(0.5f * th);
        const float hs = 0.5f * (phi + om), hd = 0.5f * (phi - om);
        const float2 m00 = make_float2(c * cosf(hs), -c * sinf(hs));
        const float2 m01 = make_float2(-s * cosf(hd), -s * sinf(hd));
        const float2 m10 = make_float2(s * cosf(hd), -s * sinf(hd));
        const float2 m11 = make_float2(c * cosf(hs), c * sinf(hs));
        for (int p = tid; p < 512; p += 256) {
            const int lo = p & 15;
            const int i0 = ((p - lo) << 1) | lo;
            const int i1 = i0 | 16;
            const float2 t0 = psi[i0], t1 = psi[i1];
            psi[i0] = cadd(cmul(m00, t0), cmul(m01, t1));
            psi[i1] = cadd(cmul(m10, t0), cmul(m11, t1));
        }
    }
    __syncthreads();

    float ev[10];
#pragma unroll
    for (int k = 0; k < 10; k++) {
        const int bsh = 9 - k;
        const int mlo = (1 << bsh) - 1;
        float part = 0.0f;
        for (int p = tid; p < 512; p += 256) {
            const int i0 = ((p >> bsh) << (bsh + 1)) | (p & mlo);
            const int i1 = i0 | (1 << bsh);
            const float2 a0 = psi[i0], a1 = psi[i1];
            part += a0.x * a1.y - a0.y * a1.x;
        }
#pragma unroll
        for (int off = 16; off > 0; off >>= 1)
            part += __shfl_down_sync(0xffffffffu, part, off);
        if (lane == 0) sred[wid] = part;
        __syncthreads();
        if (tid == 0) {
            float s = 0.0f;
            for (int w = 0; w < 8; w++) s += sred[w];
            ev[k] = 2.0f * s;
        }
        __syncthreads();
    }

    if (tid == 0) {
        float m = ev[0];
#pragma unroll
        for (int k = 1; k < 10; k++) m = fmaxf(m, ev[k]);
        float ssum = 0.0f;
#pragma unroll
        for (int k = 0; k < 10; k++) ssum += expf(ev[k] - m);
        const float l = logf(ssum);
#pragma unroll
        for (int k = 0; k < 10; k++)
            out[(size_t)b * 10 + k] = ev[k] - m - l;
    }
}

// ---------------------------------------------------------------------------
// launch
// ---------------------------------------------------------------------------
extern "C" void kernel_launch(void* const* d_in, const int* in_sizes, int n_in,
                              void* d_out, int out_size)
{
    const float* x        = (const float*)d_in[0];
    const float* conv1_w  = (const float*)d_in[1];
    const float* conv1_b  = (const float*)d_in[2];
    const float* conv2_w  = (const float*)d_in[3];
    const float* conv2_b  = (const float*)d_in[4];
    const float* fc1_w    = (const float*)d_in[5];
    const float* fc1_b    = (const float*)d_in[6];
    const float* fc2_w    = (const float*)d_in[7];
    const float* fc2_b    = (const float*)d_in[8];
    const float* theta0   = (const float*)d_in[9];
    const float* theta_rz = (const float*)d_in[10];
    const float* theta_ps = (const float*)d_in[11];
    const float* rot_p    = (const float*)d_in[12];
    float* out = (float*)d_out;

    // sIn 45968 + sx 3136 + sw1 1152 + sb1 128 + sb2 256 = 50640 B
    const int conv_smem = 50640;
    cudaFuncSetAttribute(conv12_kernel, cudaFuncAttributeMaxDynamicSharedMemorySize,
                         conv_smem);

    prep_wfrag_kernel<<<18, 128>>>(conv2_w);
    prep_fc1w_kernel<<<(128 * 9216) / 256, 256>>>(fc1_w);
    conv12_kernel<<<BATCH, 256, conv_smem>>>(x, conv1_w, conv1_b, conv2_b);
    fc1_part_kernel<<<dim3(BATCH / 32, 8), 256>>>();
    fc1_reduce_kernel<<<(BATCH * 128) / 256, 256>>>(fc1_b);
    qsim_kernel<<<BATCH, 256>>>(fc2_w, fc2_b, theta0, theta_rz, theta_ps, rot_p, out);
}

// round 5
// speedup vs baseline: 7.4558x; 1.5725x over previous
#include <cuda_runtime.h>
#include <cuda_bf16.h>
#include <math.h>
#include <stdint.h>

// ---------------------------------------------------------------------------
// Net_23553600651528: [conv1 fused into conv2 block] -> conv2 (bf16 mma,
// ldmatrix A, 32 M-rows/warp) + relu + maxpool (bf16 out) ->
// fc1 (bf16 mma, K-split) -> [fc2+sigmoid -> 10-qubit statevector -> <Y> ->
// log_softmax].  B = 2048.
// ---------------------------------------------------------------------------

#define BATCH 2048

// scratch (__device__ globals; allocation-free rule)
__device__ __nv_bfloat16 g_poolh[BATCH * 9216]; // pooled conv2 bf16, [b][quad*64+oc]
__device__ float g_fc1[BATCH * 128];            // fc1 output
__device__ float g_part[8 * BATCH * 128];       // fc1 K-split partials
__device__ uint4 g_wfragb[18 * 4 * 32];         // conv2 weights, bf16 B-fragments
__device__ float g_fc1wp[128 * 9216];           // fc1 weights fp32, K permuted
__device__ uint4 g_fc1wfrag[576 * 8 * 32];      // fc1 weights, bf16 B-fragments

__device__ __forceinline__ uint32_t packbf(float lo, float hi) {
    __nv_bfloat162 h2 = __floats2bfloat162_rn(lo, hi);   // .x=lo -> low 16 bits
    return *reinterpret_cast<uint32_t*>(&h2);
}

__device__ __forceinline__ void mma_bf16(float& c0, float& c1, float& c2, float& c3,
                                         uint32_t a0, uint32_t a1, uint32_t a2, uint32_t a3,
                                         uint32_t b0, uint32_t b1) {
    asm volatile("mma.sync.aligned.m16n8k16.row.col.f32.bf16.bf16.f32 "
                 "{%0,%1,%2,%3}, {%4,%5,%6,%7}, {%8,%9}, {%0,%1,%2,%3};"
                 : "+f"(c0), "+f"(c1), "+f"(c2), "+f"(c3)
                 : "r"(a0), "r"(a1), "r"(a2), "r"(a3), "r"(b0), "r"(b1));
}

__device__ __forceinline__ void ldmx4(uint32_t& a0, uint32_t& a1,
                                      uint32_t& a2, uint32_t& a3, uint32_t addr) {
    asm volatile("ldmatrix.sync.aligned.m8n8.x4.shared.b16 {%0,%1,%2,%3}, [%4];"
                 : "=r"(a0), "=r"(a1), "=r"(a2), "=r"(a3) : "r"(addr));
}

// ---------------------------------------------------------------------------
// prep: conv2 weights -> bf16 B-fragments (m16n8k16).  k = r*32+ic, step s:
// r=s>>1, icb=(s&1)*16.  uint4 = (b0,b1) pairs for oc-frags 2p, 2p+1.
// ---------------------------------------------------------------------------
__global__ void prep_wfrag_kernel(const float* __restrict__ w2)
{
    const int s = blockIdx.x;          // 0..17
    const int tid = threadIdx.x;       // 0..127
    const int p = tid >> 5;
    const int lane = tid & 31;
    const int g = lane >> 2, c = lane & 3;
    const int r = s >> 1;
    const int icb = (s & 1) * 16;
    const int oc_a = (2 * p) * 8 + g;
    const int oc_b = oc_a + 8;
    const int i00 = icb + 2 * c, i01 = i00 + 1;
    const int i10 = i00 + 8,     i11 = i10 + 1;
#define WV(ic, oc) w2[(oc) * 288 + (ic) * 9 + r]
    uint4 v;
    v.x = packbf(WV(i00, oc_a), WV(i01, oc_a));
    v.y = packbf(WV(i10, oc_a), WV(i11, oc_a));
    v.z = packbf(WV(i00, oc_b), WV(i01, oc_b));
    v.w = packbf(WV(i10, oc_b), WV(i11, oc_b));
#undef WV
    g_wfragb[(s * 4 + p) * 32 + lane] = v;
}

// ---------------------------------------------------------------------------
// prep: fc1 weights permuted to k' = quad*64 + oc  (fp32 intermediate)
// ---------------------------------------------------------------------------
__global__ void prep_fc1w_kernel(const float* __restrict__ fc1_w)
{
    const int i = blockIdx.x * 256 + threadIdx.x;
    const int n = i / 9216;
    const int kp = i - n * 9216;
    const int quad = kp >> 6;
    const int oc = kp & 63;
    g_fc1wp[i] = fc1_w[n * 9216 + oc * 144 + quad];
}

// ---------------------------------------------------------------------------
// prep: fc1 permuted weights -> bf16 B-fragments.  576 k-steps, 16 n-frags
// packed as 8 uint4 pairs.  Coalesced float2 reads from g_fc1wp.
// ---------------------------------------------------------------------------
__global__ void prep_fc1frag_kernel()
{
    const int s = blockIdx.x;          // 0..575
    const int tid = threadIdx.x;       // 0..255
    const int p = tid >> 5;            // n-frag pair 0..7
    const int lane = tid & 31;
    const int g = lane >> 2, c = lane & 3;
    const int k0 = s * 16;
    const int n_a = (2 * p) * 8 + g;
    const int n_b = n_a + 8;
    const float2 wa0 = *(const float2*)(g_fc1wp + (size_t)n_a * 9216 + k0 + 2 * c);
    const float2 wa1 = *(const float2*)(g_fc1wp + (size_t)n_a * 9216 + k0 + 2 * c + 8);
    const float2 wb0 = *(const float2*)(g_fc1wp + (size_t)n_b * 9216 + k0 + 2 * c);
    const float2 wb1 = *(const float2*)(g_fc1wp + (size_t)n_b * 9216 + k0 + 2 * c + 8);
    uint4 v;
    v.x = packbf(wa0.x, wa0.y);
    v.y = packbf(wa1.x, wa1.y);
    v.z = packbf(wb0.x, wb0.y);
    v.w = packbf(wb1.x, wb1.y);
    g_fc1wfrag[(s * 8 + p) * 32 + lane] = v;
}

// ---------------------------------------------------------------------------
// fused conv1+conv2: one block per batch element, 256 threads / 8 warps.
//   conv1+relu -> smem bf16, position-major, 80 B (40 bf16) per position
//   (16B-aligned rows for ldmatrix; 4 pad words never read).
//   conv2: warp handles 32 M rows (2 A-frags sharing each B-frag); A via
//   ldmatrix.x4, B via LDG (L1/L2-hot); 18 warp-tiles over 3 rounds.
//   epilogue: 2x2 maxpool via shfl_xor, bias+relu, bf16 store [quad][oc].
// ---------------------------------------------------------------------------
__global__ void __launch_bounds__(256) conv12_kernel(const float* __restrict__ x,
                                                     const float* __restrict__ w1,
                                                     const float* __restrict__ b1,
                                                     const float* __restrict__ b2)
{
    extern __shared__ char smem[];
    __nv_bfloat16* sIn = (__nv_bfloat16*)smem;               // 676*40 bf16 = 54080 B
    float* sx  = (float*)(smem + 54080);                     // 784 f
    float* sw1 = (float*)(smem + 54080 + 3136);              // 288 f
    float* sb1 = (float*)(smem + 54080 + 3136 + 1152);       // 32 f
    float* sb2 = (float*)(smem + 54080 + 3136 + 1152 + 128); // 64 f

    const int b = blockIdx.x;
    const int tid = threadIdx.x;
    const int w = tid >> 5;
    const int lane = tid & 31;

    // ---- stage inputs ----
    for (int i = tid; i < 784; i += 256) sx[i] = x[b * 784 + i];
    for (int i = tid; i < 288; i += 256) sw1[i] = w1[i];
    if (tid < 32) sb1[tid] = b1[tid];
    for (int i = tid; i < 64; i += 256) sb2[i] = b2[i];
    __syncthreads();

    // ---- conv1 + relu -> sIn (bf16, 40 bf16 / position) ----
    for (int p = tid; p < 676; p += 256) {
        const int oy = p / 26, ox = p % 26;
        float in[9];
#pragma unroll
        for (int kh = 0; kh < 3; kh++)
#pragma unroll
            for (int kw = 0; kw < 3; kw++)
                in[kh * 3 + kw] = sx[(oy + kh) * 28 + ox + kw];
        uint32_t* dst = (uint32_t*)(sIn + p * 40);
#pragma unroll 4
        for (int oc2 = 0; oc2 < 16; oc2++) {
            float va = sb1[2 * oc2], vb = sb1[2 * oc2 + 1];
            const float* wa = sw1 + (2 * oc2) * 9;
#pragma unroll
            for (int j = 0; j < 9; j++) { va += wa[j] * in[j]; vb += wa[9 + j] * in[j]; }
            dst[oc2] = packbf(fmaxf(va, 0.0f), fmaxf(vb, 0.0f));
        }
    }
    __syncthreads();

    // ---- conv2 GEMM: 18 warp-tiles of 32 M rows over 3 rounds ----
    const uint32_t sbase = (uint32_t)__cvta_generic_to_shared(sIn);
    __nv_bfloat16* outB = g_poolh + (size_t)b * 9216;

    const int rl = lane & 15;          // row within a 16-row A frag
    const int half16 = (lane >> 4) * 16;

    for (int rd = 0; rd < 3; rd++) {
        const int wt = rd * 8 + w;     // warp-tile 0..17
        if (wt >= 18) break;
        const int qb = wt * 8;         // 8 quads (32 rows) per warp-tile

        // per-lane row base addresses for the two A frags
        uint32_t ra0, ra1;
        {
            int quad = qb + (rl >> 2), e = rl & 3;
            int qy = quad / 12, qx = quad - qy * 12;
            int pos = (2 * qy + (e >> 1)) * 26 + 2 * qx + (e & 1);
            ra0 = sbase + pos * 80 + half16;
            quad = qb + 4 + (rl >> 2);
            qy = quad / 12; qx = quad - qy * 12;
            pos = (2 * qy + (e >> 1)) * 26 + 2 * qx + (e & 1);
            ra1 = sbase + pos * 80 + half16;
        }

        float accA[8][4], accB[8][4];
#pragma unroll
        for (int n = 0; n < 8; n++) {
            accA[n][0] = 0.f; accA[n][1] = 0.f; accA[n][2] = 0.f; accA[n][3] = 0.f;
            accB[n][0] = 0.f; accB[n][1] = 0.f; accB[n][2] = 0.f; accB[n][3] = 0.f;
        }

#pragma unroll
        for (int r = 0; r < 9; r++) {
            const uint32_t khw80 = (uint32_t)(((r / 3) * 26 + (r % 3)) * 80);
#pragma unroll
            for (int h = 0; h < 2; h++) {
                uint32_t a0, a1, a2, a3, e0, e1, e2, e3;
                ldmx4(a0, a1, a2, a3, ra0 + khw80 + h * 32);
                ldmx4(e0, e1, e2, e3, ra1 + khw80 + h * 32);
                const uint4* wf = g_wfragb + (r * 2 + h) * 128;
#pragma unroll
                for (int p4 = 0; p4 < 4; p4++) {
                    const uint4 bq = wf[p4 * 32 + lane];
                    mma_bf16(accA[2 * p4][0], accA[2 * p4][1], accA[2 * p4][2], accA[2 * p4][3],
                             a0, a1, a2, a3, bq.x, bq.y);
                    mma_bf16(accA[2 * p4 + 1][0], accA[2 * p4 + 1][1],
                             accA[2 * p4 + 1][2], accA[2 * p4 + 1][3],
                             a0, a1, a2, a3, bq.z, bq.w);
                    mma_bf16(accB[2 * p4][0], accB[2 * p4][1], accB[2 * p4][2], accB[2 * p4][3],
                             e0, e1, e2, e3, bq.x, bq.y);
                    mma_bf16(accB[2 * p4 + 1][0], accB[2 * p4 + 1][1],
                             accB[2 * p4 + 1][2], accB[2 * p4 + 1][3],
                             e0, e1, e2, e3, bq.z, bq.w);
                }
            }
        }

        // epilogue for both frags: maxpool via shfl_xor, bias+relu, bf16 store
        const int hh = lane >> 4;
        const int rr = lane & 3;
        const bool writer = ((lane & 12) == 0);
#pragma unroll
        for (int f = 0; f < 2; f++) {
            const int qf = qb + f * 4;
#pragma unroll
            for (int n = 0; n < 8; n++) {
                float v0 = f ? accB[n][0] : accA[n][0];
                float v1 = f ? accB[n][1] : accA[n][1];
                float v2 = f ? accB[n][2] : accA[n][2];
                float v3 = f ? accB[n][3] : accA[n][3];
#pragma unroll
                for (int d = 4; d <= 8; d <<= 1) {
                    v0 = fmaxf(v0, __shfl_xor_sync(0xffffffffu, v0, d));
                    v1 = fmaxf(v1, __shfl_xor_sync(0xffffffffu, v1, d));
                    v2 = fmaxf(v2, __shfl_xor_sync(0xffffffffu, v2, d));
                    v3 = fmaxf(v3, __shfl_xor_sync(0xffffffffu, v3, d));
                }
                if (writer) {
                    const int oc = n * 8 + 2 * rr;
                    const float ba = sb2[oc], bb = sb2[oc + 1];
                    *(uint32_t*)(outB + (qf + hh) * 64 + oc) =
                        packbf(fmaxf(v0 + ba, 0.f), fmaxf(v1 + bb, 0.f));
                    *(uint32_t*)(outB + (qf + 2 + hh) * 64 + oc) =
                        packbf(fmaxf(v2 + ba, 0.f), fmaxf(v3 + bb, 0.f));
                }
            }
        }
    }
}

// ---------------------------------------------------------------------------
// fc1 bf16 tensor-core with K-split: grid (16 Mblocks, 8 ksplits), 256 thr.
// Warp w owns M rows Mb*128 + w*16 .. +15; N = full 128 (16 n-frags).
// A frags: per-lane LDG.32 from g_poolh (a0/a2 share 32B sectors).
// B frags: LDG.128 from g_fc1wfrag (L2-resident).  72 k-steps per split.
// ---------------------------------------------------------------------------
__global__ void __launch_bounds__(256) fc1_part_kernel()
{
    const int tid = threadIdx.x;
    const int w = tid >> 5;
    const int lane = tid & 31;
    const int Mb = blockIdx.x;         // 0..15
    const int ks = blockIdx.y;         // 0..7
    const int m0 = Mb * 128 + w * 16;
    const int g = lane >> 2, c = lane & 3;

    float acc[16][4];
#pragma unroll
    for (int f = 0; f < 16; f++) {
        acc[f][0] = 0.f; acc[f][1] = 0.f; acc[f][2] = 0.f; acc[f][3] = 0.f;
    }

    const __nv_bfloat16* A0 = g_poolh + (size_t)(m0 + g) * 9216;
    const __nv_bfloat16* A1 = g_poolh + (size_t)(m0 + g + 8) * 9216;

    for (int step = 0; step < 72; step++) {
        const int k0 = ks * 1152 + step * 16;
        const uint32_t a0 = *(const uint32_t*)(A0 + k0 + 2 * c);
        const uint32_t a1 = *(const uint32_t*)(A1 + k0 + 2 * c);
        const uint32_t a2 = *(const uint32_t*)(A0 + k0 + 2 * c + 8);
        const uint32_t a3 = *(const uint32_t*)(A1 + k0 + 2 * c + 8);
        const uint4* wf = g_fc1wfrag + (size_t)(ks * 72 + step) * 256;
#pragma unroll
        for (int p4 = 0; p4 < 8; p4++) {
            const uint4 bq = wf[p4 * 32 + lane];
            mma_bf16(acc[2 * p4][0], acc[2 * p4][1], acc[2 * p4][2], acc[2 * p4][3],
                     a0, a1, a2, a3, bq.x, bq.y);
            mma_bf16(acc[2 * p4 + 1][0], acc[2 * p4 + 1][1],
                     acc[2 * p4 + 1][2], acc[2 * p4 + 1][3],
                     a0, a1, a2, a3, bq.z, bq.w);
        }
    }

    float* dst = g_part + (size_t)ks * BATCH * 128;
#pragma unroll
    for (int f = 0; f < 16; f++) {
        const int n0 = f * 8 + 2 * c;
        *(float2*)(dst + (size_t)(m0 + g) * 128 + n0) = make_float2(acc[f][0], acc[f][1]);
        *(float2*)(dst + (size_t)(m0 + g + 8) * 128 + n0) = make_float2(acc[f][2], acc[f][3]);
    }
}

__global__ void fc1_reduce_kernel(const float* __restrict__ bias)
{
    const int i = blockIdx.x * 256 + threadIdx.x;
    float s = 0.0f;
#pragma unroll
    for (int ks = 0; ks < 8; ks++) s += g_part[(size_t)ks * BATCH * 128 + i];
    s += bias[i & 127];
    g_fc1[i] = fmaxf(s, 0.0f);
}

// ---------------------------------------------------------------------------
// quantum kernel; wire w <-> bit (9-w)
// ---------------------------------------------------------------------------
__device__ __forceinline__ float2 cmul(float2 a, float2 b) {
    return make_float2(a.x * b.x - a.y * b.y, a.x * b.y + a.y * b.x);
}
__device__ __forceinline__ float2 cadd(float2 a, float2 b) {
    return make_float2(a.x + b.x, a.y + b.y);
}

__global__ void qsim_kernel(const float* __restrict__ fc2w,
                            const float* __restrict__ fc2b,
                            const float* __restrict__ theta0,
                            const float* __restrict__ theta_rz,
                            const float* __restrict__ theta_ps,
                            const float* __restrict__ rot_p,
                            float* __restrict__ out)
{
    __shared__ float sh[128];
    __shared__ float sang[10];
    __shared__ float2 svec[10][2];
    __shared__ float2 psi[1024];
    __shared__ float sred[8];

    const int b = blockIdx.x;
    const int tid = threadIdx.x;
    const int wid = tid >> 5, lane = tid & 31;

    if (tid < 128) sh[tid] = g_fc1[(size_t)b * 128 + tid];
    __syncthreads();

    if (tid < 10) {
        float z = fc2b[tid];
        const float* wr = fc2w + tid * 128;
        for (int k = 0; k < 128; k++) z += sh[k] * wr[k];
        const float a = 6.2831853071795864f / (1.0f + expf(-z));
        sang[tid] = a;

        float alpha = theta0[tid] + a;
        if (tid == 1) alpha += a;
        if (tid == 5) alpha -= 0.78539816339745f;
        const float c = cosf(0.5f * alpha);
        const float s = sinf(0.5f * alpha);
        float2 v0 = make_float2(c, 0.0f);
        float2 v1 = make_float2(0.0f, -s);

        if (tid == 2) {
            const float cy = cosf(0.5f * a), sy = sinf(0.5f * a);
            v0 = make_float2(cy * c, sy * s);
            v1 = make_float2(sy * c, -cy * s);
        } else if (tid == 3) {
            const float2 e = make_float2(cosf(0.5f * a), -sinf(0.5f * a));
            v0 = cmul(v0, e);
            v1 = cmul(v1, make_float2(e.x, -e.y));
        } else if (tid == 4) {
            v1 = make_float2(s, 0.0f);
        } else if (tid == 5) {
            const float r = 0.70710678118654752f;
            v1 = make_float2(s * r, -s * r);
        } else if (tid == 6) {
            const float t = theta_rz[0];
            const float2 e = make_float2(cosf(0.5f * t), -sinf(0.5f * t));
            v0 = cmul(v0, e);
            v1 = cmul(v1, make_float2(e.x, -e.y));
        } else if (tid == 7) {
            const float h0 = 0.5f * (c - s), h1 = 0.5f * (c + s);
            v0 = make_float2(h0, h0);
            v1 = make_float2(h1, -h1);
        }
        svec[tid][0] = v0;
        svec[tid][1] = v1;
    }
    __syncthreads();

    for (int i = tid; i < 1024; i += 256) {
        float2 p = svec[0][(i >> 9) & 1];
#pragma unroll
        for (int k = 1; k < 10; k++)
            p = cmul(p, svec[k][(i >> (9 - k)) & 1]);
        if (i & 512) p = make_float2(p.y, -p.x);
        psi[i] = p;
    }
    __syncthreads();

    for (int p = tid; p < 512; p += 256) {
        const int i0 = ((p & ~1) << 1) | (p & 1);
        if (i0 & 64) {
            const int i1 = i0 | 2;
            const float2 t0 = psi[i0], t1 = psi[i1];
            psi[i0] = make_float2(t1.y, -t1.x);
            psi[i1] = make_float2(-t0.y, t0.x);
        }
    }
    __syncthreads();

    for (int i = tid; i < 1024; i += 256) {
        if ((i & 192) == 128) {
            const int j = i ^ 192;
            const float2 t = psi[i]; psi[i] = psi[j]; psi[j] = t;
        }
    }
    __syncthreads();

    for (int i = tid; i < 1024; i += 256) {
        if ((i & 32) && ((i & 24) == 16)) {
            const int j = i ^ 24;
            const float2 t = psi[i]; psi[i] = psi[j]; psi[j] = t;
        }
    }
    __syncthreads();

    for (int p = tid; p < 512; p += 256) {
        if ((p & 18) == 18) {
            const int j = p | 512;
            const float2 t = psi[p]; psi[p] = psi[j]; psi[j] = t;
        }
    }
    __syncthreads();

    {
        const float tps = theta_ps[0];
        const float a7 = sang[7];
        const float2 e8 = make_float2(cosf(tps), sinf(tps));
        const float2 e7 = make_float2(cosf(a7), sinf(a7));
        for (int i = tid; i < 1024; i += 256) {
            float2 v = psi[i];
            if (i & 2) v = cmul(v, e8);
            if (i & 4) v = cmul(v, e7);
            psi[i] = v;
        }
    }
    __syncthreads();

    {
        const float phi = rot_p[0], th = rot_p[1], om = rot_p[2];
        const float c = cosf(0.5f * th), s = sinf(0.5f * th);
        const float hs = 0.5f * (phi + om), hd = 0.5f * (phi - om);
        const float2 m00 = make_float2(c * cosf(hs), -c * sinf(hs));
        const float2 m01 = make_float2(-s * cosf(hd), -s * sinf(hd));
        const float2 m10 = make_float2(s * cosf(hd), -s * sinf(hd));
        const float2 m11 = make_float2(c * cosf(hs), c * sinf(hs));
        for (int p = tid; p < 512; p += 256) {
            const int lo = p & 31;
            const int i0 = ((p - lo) << 1) | lo;
            const int i1 = i0 | 32;
            const float2 t0 = psi[i0], t1 = psi[i1];
            psi[i0] = cadd(cmul(m00, t0), cmul(m01, t1));
            psi[i1] = cadd(cmul(m10, t0), cmul(m11, t1));
        }
    }
    __syncthreads();

    {
        const float phi = sang[6], th = sang[7], om = sang[8];
        const float c = cosf(0.5f * th), s = sinf(0.5f * th);
        const float hs = 0.5f * (phi + om), hd = 0.5f * (phi - om);
        const float2 m00 = make_float2(c * cosf(hs), -c * sinf(hs));
        const float2 m01 = make_float2(-s * cosf(hd), -s * sinf(hd));
        const float2 m10 = make_float2(s * cosf(hd), -s * sinf(hd));
        const float2 m11 = make_float2(c * cosf(hs), c * sinf(hs));
        for (int p = tid; p < 512; p += 256) {
            const int lo = p & 15;
            const int i0 = ((p - lo) << 1) | lo;
            const int i1 = i0 | 16;
            const float2 t0 = psi[i0], t1 = psi[i1];
            psi[i0] = cadd(cmul(m00, t0), cmul(m01, t1));
            psi[i1] = cadd(cmul(m10, t0), cmul(m11, t1));
        }
    }
    __syncthreads();

    float ev[10];
#pragma unroll
    for (int k = 0; k < 10; k++) {
        const int bsh = 9 - k;
        const int mlo = (1 << bsh) - 1;
        float part = 0.0f;
        for (int p = tid; p < 512; p += 256) {
            const int i0 = ((p >> bsh) << (bsh + 1)) | (p & mlo);
            const int i1 = i0 | (1 << bsh);
            const float2 a0 = psi[i0], a1 = psi[i1];
            part += a0.x * a1.y - a0.y * a1.x;
        }
#pragma unroll
        for (int off = 16; off > 0; off >>= 1)
            part += __shfl_down_sync(0xffffffffu, part, off);
        if (lane == 0) sred[wid] = part;
        __syncthreads();
        if (tid == 0) {
            float s = 0.0f;
            for (int w = 0; w < 8; w++) s += sred[w];
            ev[k] = 2.0f * s;
        }
        __syncthreads();
    }

    if (tid == 0) {
        float m = ev[0];
#pragma unroll
        for (int k = 1; k < 10; k++) m = fmaxf(m, ev[k]);
        float ssum = 0.0f;
#pragma unroll
        for (int k = 0; k < 10; k++) ssum += expf(ev[k] - m);
        const float l = logf(ssum);
#pragma unroll
        for (int k = 0; k < 10; k++)
            out[(size_t)b * 10 + k] = ev[k] - m - l;
    }
}

// ---------------------------------------------------------------------------
// launch
// ---------------------------------------------------------------------------
extern "C" void kernel_launch(void* const* d_in, const int* in_sizes, int n_in,
                              void* d_out, int out_size)
{
    const float* x        = (const float*)d_in[0];
    const float* conv1_w  = (const float*)d_in[1];
    const float* conv1_b  = (const float*)d_in[2];
    const float* conv2_w  = (const float*)d_in[3];
    const float* conv2_b  = (const float*)d_in[4];
    const float* fc1_w    = (const float*)d_in[5];
    const float* fc1_b    = (const float*)d_in[6];
    const float* fc2_w    = (const float*)d_in[7];
    const float* fc2_b    = (const float*)d_in[8];
    const float* theta0   = (const float*)d_in[9];
    const float* theta_rz = (const float*)d_in[10];
    const float* theta_ps = (const float*)d_in[11];
    const float* rot_p    = (const float*)d_in[12];
    float* out = (float*)d_out;

    // sIn 54080 + sx 3136 + sw1 1152 + sb1 128 + sb2 256 = 58752 B
    const int conv_smem = 58752;
    cudaFuncSetAttribute(conv12_kernel, cudaFuncAttributeMaxDynamicSharedMemorySize,
                         conv_smem);

    prep_wfrag_kernel<<<18, 128>>>(conv2_w);
    prep_fc1w_kernel<<<(128 * 9216) / 256, 256>>>(fc1_w);
    prep_fc1frag_kernel<<<576, 256>>>();
    conv12_kernel<<<BATCH, 256, conv_smem>>>(x, conv1_w, conv1_b, conv2_b);
    fc1_part_kernel<<<dim3(16, 8), 256>>>();
    fc1_reduce_kernel<<<(BATCH * 128) / 256, 256>>>(fc1_b);
    qsim_kernel<<<BATCH, 256>>>(fc2_w, fc2_b, theta0, theta_rz, theta_ps, rot_p, out);
}